// round 2
// baseline (speedup 1.0000x reference)
#include <cuda_runtime.h>
#include <math.h>

// Problem dims
#define T_STEPS 512
#define B 256
#define D 256
#define H 512
#define G4 2048        // 4*H (LSTM gates)
#define ZW 3584        // 3*H (gi) + 3*H (gh) + H (h3)
#define NBLK 128       // persistent grid: (B/32) * (H/32) = 8*16

// ---------------- device scratch (no allocation allowed) ----------------
__device__ float g_Xproj[(size_t)T_STEPS * B * G4]; // per-step input projection + biases
__device__ float g_Whc[G4 * H];                     // Wih[:,D:] + Whh   [j][k]
__device__ float g_M[H * H];                        // phase @ fe_W^T    [k][j]
__device__ float g_Wbig[H * ZW];                    // [k][j]: [M@Wih_g^T | M@Whh_g^T | M]
__device__ float g_bbig[ZW];
__device__ float g_hx[B * H];
__device__ float g_cx[B * H];
__device__ float g_h1[B * H];

// grid-barrier state (persists across graph replays; gen is re-read at entry)
__device__ unsigned g_count = 0;
__device__ volatile unsigned g_sense = 0;

__device__ __forceinline__ float sigmoidf_(float x) {
    return 1.0f / (1.0f + expf(-x));
}

// ---------------- init ----------------
__global__ void k_init() {
    int i = blockIdx.x * blockDim.x + threadIdx.x;
    if (i < B * H) { g_hx[i] = 0.0f; g_cx[i] = 0.0f; }
}

// ---------------- Whc = Wih[:, D:] + Whh ----------------
__global__ void k_whc(const float* __restrict__ Wih, const float* __restrict__ Whh) {
    int idx = blockIdx.x * blockDim.x + threadIdx.x;
    if (idx < G4 * H) {
        int j = idx >> 9;
        int k = idx & 511;
        g_Whc[idx] = Wih[(size_t)j * (D + H) + D + k] + Whh[idx];
    }
}

// ---------------- generic NT GEMM (precompute only) ----------------
__global__ __launch_bounds__(256) void gemm_nt(
    const float* __restrict__ A, const float* __restrict__ Bm, float* __restrict__ C,
    const float* __restrict__ bias1, const float* __restrict__ bias2,
    int K, int lda, int ldb, int ldc, int coloff)
{
    __shared__ float sA[32][33];
    __shared__ float sB[32][33];
    int t = threadIdx.x;
    int i0 = blockIdx.x * 32, j0 = blockIdx.y * 32;
    int tx = t & 15, ty = t >> 4;
    float a00 = 0.f, a01 = 0.f, a10 = 0.f, a11 = 0.f;
    for (int l0 = 0; l0 < K; l0 += 32) {
        #pragma unroll
        for (int i = 0; i < 4; i++) {
            int e = t + i * 256; int r = e >> 5, cc = e & 31;
            sA[r][cc] = A[(size_t)(i0 + r) * lda + l0 + cc];
            sB[r][cc] = Bm[(size_t)(j0 + r) * ldb + l0 + cc];
        }
        __syncthreads();
        #pragma unroll
        for (int ll = 0; ll < 32; ll++) {
            float x0 = sA[ty * 2][ll],     x1 = sA[ty * 2 + 1][ll];
            float y0 = sB[tx * 2][ll],     y1 = sB[tx * 2 + 1][ll];
            a00 += x0 * y0; a01 += x0 * y1; a10 += x1 * y0; a11 += x1 * y1;
        }
        __syncthreads();
    }
    int iR = i0 + ty * 2;
    int jC = j0 + tx * 2;
    float acc[2][2] = {{a00, a01}, {a10, a11}};
    #pragma unroll
    for (int r = 0; r < 2; r++) {
        #pragma unroll
        for (int c = 0; c < 2; c++) {
            float v = acc[r][c];
            int j = jC + c;
            if (bias1) v += bias1[j];
            if (bias2) v += bias2[j];
            C[(size_t)(iR + r) * ldc + coloff + j] = v;
        }
    }
}

// ---------------- copy M into Wbig block 6 ----------------
__global__ void k_copyM() {
    int idx = blockIdx.x * blockDim.x + threadIdx.x;
    if (idx < H * H) {
        int k = idx >> 9, j = idx & 511;
        g_Wbig[(size_t)k * ZW + 3072 + j] = g_M[idx];
    }
}

// ---------------- fused bias ----------------
__global__ void k_bbig(const float* __restrict__ feb,
                       const float* __restrict__ gWih, const float* __restrict__ gWhh,
                       const float* __restrict__ gbih, const float* __restrict__ gbhh) {
    int j = blockIdx.x * blockDim.x + threadIdx.x;
    if (j >= ZW) return;
    float s;
    if (j < 1536) {
        const float* w = gWih + (size_t)j * H;
        s = gbih[j];
        for (int k = 0; k < H; k++) s += feb[k] * w[k];
    } else if (j < 3072) {
        int jj = j - 1536;
        const float* w = gWhh + (size_t)jj * H;
        s = gbhh[jj];
        for (int k = 0; k < H; k++) s += feb[k] * w[k];
    } else {
        s = feb[j - 3072];
    }
    g_bbig[j] = s;
}

// ---------------- software grid barrier (all NBLK blocks resident) ----------------
__device__ __forceinline__ void grid_barrier(unsigned& gen) {
    __syncthreads();
    if (threadIdx.x == 0) {
        __threadfence();  // publish this block's global writes
        if (atomicAdd(&g_count, 1u) == NBLK - 1) {
            g_count = 0;
            __threadfence();
            g_sense = gen + 1;  // release
        } else {
            while (g_sense == gen) { }
            __threadfence();
        }
        gen = gen + 1;
    }
    __syncthreads();
}

// ---------------- persistent recurrence kernel: all 512 steps ----------------
// grid = 128 blocks x 256 threads, all co-resident.
// Block (bq, jq): bq = bid & 7 -> batch rows b0..b0+31; jq = bid >> 3 -> cols j0..j0+31.
__global__ __launch_bounds__(256) void k_recur(float* __restrict__ out) {
    __shared__ float sHT[32][36];       // hidden tile, k-major: sHT[k][row]
    __shared__ float sW[7][32][36];     // weight tiles (stage1: [blk][col][k], stage2: [blk][k][col])

    int tid = threadIdx.x;
    int bid = blockIdx.x;
    int b0 = (bid & 7) * 32;
    int j0 = (bid >> 3) * 32;
    int c   = tid & 31;           // output column within tile
    int rg  = tid >> 5;           // row group: rows rg*4 .. rg*4+3
    int kk4 = (tid & 7) * 4;      // float4 k-offset for loads
    int r8  = tid >> 3;           // 0..31: row/col index for loads
    int h   = j0 + c;

    unsigned gen = 0;
    if (tid == 0) gen = g_sense;  // survive graph replays

    for (int t = 0; t < T_STEPS; t++) {
        float acc[7][4];

        // ================= stage 1: LSTM gates =================
        #pragma unroll
        for (int blk = 0; blk < 4; blk++)
            #pragma unroll
            for (int i = 0; i < 4; i++) acc[blk][i] = 0.f;

        for (int k0 = 0; k0 < H; k0 += 32) {
            // hx tile (cross-block producer -> bypass L1), store transposed
            {
                float4 v = __ldcg(reinterpret_cast<const float4*>(
                    &g_hx[(b0 + r8) * H + k0 + kk4]));
                sHT[kk4 + 0][r8] = v.x;
                sHT[kk4 + 1][r8] = v.y;
                sHT[kk4 + 2][r8] = v.z;
                sHT[kk4 + 3][r8] = v.w;
            }
            // Whc tiles: sW[blk][col][k]
            #pragma unroll
            for (int blk = 0; blk < 4; blk++) {
                float4 w = *reinterpret_cast<const float4*>(
                    &g_Whc[(size_t)(blk * H + j0 + r8) * H + k0 + kk4]);
                *reinterpret_cast<float4*>(&sW[blk][r8][kk4]) = w;
            }
            __syncthreads();
            #pragma unroll
            for (int kk = 0; kk < 32; kk++) {
                float4 x = *reinterpret_cast<const float4*>(&sHT[kk][rg * 4]);
                #pragma unroll
                for (int blk = 0; blk < 4; blk++) {
                    float w = sW[blk][c][kk];
                    acc[blk][0] += x.x * w;
                    acc[blk][1] += x.y * w;
                    acc[blk][2] += x.z * w;
                    acc[blk][3] += x.w * w;
                }
            }
            __syncthreads();
        }
        #pragma unroll
        for (int i = 0; i < 4; i++) {
            int b = b0 + rg * 4 + i;
            size_t xb = ((size_t)t * B + b) * G4;
            float gi = acc[0][i] + __ldcs(&g_Xproj[xb + 0 * H + h]);
            float gf = acc[1][i] + __ldcs(&g_Xproj[xb + 1 * H + h]);
            float gg = acc[2][i] + __ldcs(&g_Xproj[xb + 2 * H + h]);
            float go = acc[3][i] + __ldcs(&g_Xproj[xb + 3 * H + h]);
            float iv = sigmoidf_(gi);
            float fv = sigmoidf_(gf);
            float gv = tanhf(gg);
            float ov = sigmoidf_(go);
            float cp = g_cx[b * H + h];          // same thread wrote it last step
            float cn = fv * cp + iv * gv;
            g_cx[b * H + h] = cn;
            __stcg(&g_h1[b * H + h], ov * tanhf(cn));
        }

        grid_barrier(gen);

        // ================= stage 2: phase/fe folded GRU =================
        #pragma unroll
        for (int blk = 0; blk < 7; blk++)
            #pragma unroll
            for (int i = 0; i < 4; i++) acc[blk][i] = 0.f;

        for (int k0 = 0; k0 < H; k0 += 32) {
            {
                float4 v = __ldcg(reinterpret_cast<const float4*>(
                    &g_h1[(b0 + r8) * H + k0 + kk4]));
                sHT[kk4 + 0][r8] = v.x;
                sHT[kk4 + 1][r8] = v.y;
                sHT[kk4 + 2][r8] = v.z;
                sHT[kk4 + 3][r8] = v.w;
            }
            // Wbig tiles: sW[blk][k][col]
            #pragma unroll
            for (int blk = 0; blk < 7; blk++) {
                float4 w = *reinterpret_cast<const float4*>(
                    &g_Wbig[(size_t)(k0 + r8) * ZW + blk * H + j0 + kk4]);
                *reinterpret_cast<float4*>(&sW[blk][r8][kk4]) = w;
            }
            __syncthreads();
            #pragma unroll
            for (int kk = 0; kk < 32; kk++) {
                float4 x = *reinterpret_cast<const float4*>(&sHT[kk][rg * 4]);
                #pragma unroll
                for (int blk = 0; blk < 7; blk++) {
                    float w = sW[blk][kk][c];
                    acc[blk][0] += x.x * w;
                    acc[blk][1] += x.y * w;
                    acc[blk][2] += x.z * w;
                    acc[blk][3] += x.w * w;
                }
            }
            __syncthreads();
        }
        #pragma unroll
        for (int i = 0; i < 4; i++) {
            int b = b0 + rg * 4 + i;
            float ir  = acc[0][i] + g_bbig[0 * H + h];
            float iz  = acc[1][i] + g_bbig[1 * H + h];
            float inn = acc[2][i] + g_bbig[2 * H + h];
            float hr  = acc[3][i] + g_bbig[3 * H + h];
            float hz  = acc[4][i] + g_bbig[4 * H + h];
            float hn  = acc[5][i] + g_bbig[5 * H + h];
            float h3  = acc[6][i] + g_bbig[6 * H + h];
            float r = sigmoidf_(ir + hr);
            float z = sigmoidf_(iz + hz);
            float n = tanhf(inn + r * hn);
            float hnew = (1.0f - z) * n + z * h3;
            __stcs(&out[((size_t)t * B + b) * H + h], hnew);
            __stcg(&g_hx[b * H + h], hnew);
        }

        grid_barrier(gen);
    }
}

// ---------------- finalize: append hx, cx after outputs ----------------
__global__ void k_finalize(float* __restrict__ out) {
    int i = blockIdx.x * blockDim.x + threadIdx.x;
    if (i < B * H) {
        out[(size_t)T_STEPS * B * H + i] = g_hx[i];
        out[(size_t)T_STEPS * B * H + B * H + i] = g_cx[i];
    }
}

// ---------------- host ----------------
extern "C" void kernel_launch(void* const* d_in, const int* in_sizes, int n_in,
                              void* d_out, int out_size) {
    (void)in_sizes; (void)n_in; (void)out_size;
    const float* inputs   = (const float*)d_in[0];
    const float* lstm_Wih = (const float*)d_in[1];
    const float* lstm_Whh = (const float*)d_in[2];
    const float* lstm_bih = (const float*)d_in[3];
    const float* lstm_bhh = (const float*)d_in[4];
    const float* phase    = (const float*)d_in[5];
    const float* fe_W     = (const float*)d_in[6];
    const float* fe_b     = (const float*)d_in[7];
    const float* gru_Wih  = (const float*)d_in[8];
    const float* gru_Whh  = (const float*)d_in[9];
    const float* gru_bih  = (const float*)d_in[10];
    const float* gru_bhh  = (const float*)d_in[11];
    float* out = (float*)d_out;

    float *pM, *pWbig, *pXproj;
    cudaGetSymbolAddress((void**)&pM, g_M);
    cudaGetSymbolAddress((void**)&pWbig, g_Wbig);
    cudaGetSymbolAddress((void**)&pXproj, g_Xproj);

    // state init (graph replays must be deterministic)
    k_init<<<(B * H + 255) / 256, 256>>>();

    // precompute folded weights
    k_whc<<<(G4 * H + 255) / 256, 256>>>(lstm_Wih, lstm_Whh);

    // M = phase @ fe_W^T
    gemm_nt<<<dim3(H / 32, H / 32), 256>>>(phase, fe_W, pM, nullptr, nullptr,
                                           H, H, H, H, 0);
    // Wbig[:, 0:1536] = M @ gru_Wih^T
    gemm_nt<<<dim3(H / 32, 1536 / 32), 256>>>(pM, gru_Wih, pWbig, nullptr, nullptr,
                                              H, H, H, ZW, 0);
    // Wbig[:, 1536:3072] = M @ gru_Whh^T
    gemm_nt<<<dim3(H / 32, 1536 / 32), 256>>>(pM, gru_Whh, pWbig, nullptr, nullptr,
                                              H, H, H, ZW, 1536);
    // Wbig[:, 3072:3584] = M
    k_copyM<<<(H * H + 255) / 256, 256>>>();

    // fused GRU-side bias
    k_bbig<<<(ZW + 255) / 256, 256>>>(fe_b, gru_Wih, gru_Whh, gru_bih, gru_bhh);

    // Xproj[t,b,:] = x @ Wih[:, :D]^T + bih + bhh  (big parallel GEMM)
    gemm_nt<<<dim3((T_STEPS * B) / 32, G4 / 32), 256>>>(
        inputs, lstm_Wih, pXproj, lstm_bih, lstm_bhh,
        D, D, D + H, G4, 0);

    // ONE persistent kernel for the whole recurrence (keeps graph tiny)
    k_recur<<<NBLK, 256>>>(out);

    k_finalize<<<(B * H + 255) / 256, 256>>>(out);
}